// round 7
// baseline (speedup 1.0000x reference)
#include <cuda_runtime.h>

#define Bsz 32
#define Tenc 400
#define Hd 512
#define Lsteps 100
#define Vout 511
#define KS 15
#define NBLK 128

// ---------------- persistent state ------------------------------------------
__device__ float g_hx[2][Bsz * Hd];
__device__ float g_sx[Bsz * Hd];
__device__ float g_scores[Bsz * Tenc];
__device__ unsigned g_bar;   // zeroed by bar_init before each persistent launch

__device__ __forceinline__ float warp_sum(float v) {
    #pragma unroll
    for (int o = 16; o; o >>= 1) v += __shfl_xor_sync(0xffffffffu, v, o);
    return v;
}
__device__ __forceinline__ float warp_max(float v) {
    #pragma unroll
    for (int o = 16; o; o >>= 1) v = fmaxf(v, __shfl_xor_sync(0xffffffffu, v, o));
    return v;
}

__global__ void bar_init() { g_bar = 0u; }

struct SmemT {
    union {
        struct { float ix[8][Hd]; float hx[8][Hd]; float sx[8][Hd]; } p1; // 48KB
        struct { float in[8][Hd]; } pf;                                    // 16KB
        struct { float win[128]; float part[16][100]; } p2;
        struct { float a[Tenc]; float red[16]; float4 ctx[16][32]; } p3;
    };
};

__global__ void __launch_bounds__(512, 1) seq2seq_persist(
    const float* __restrict__ x, const int* __restrict__ y,
    const float* __restrict__ emb,
    const float* __restrict__ W_ih, const float* __restrict__ W_hh,
    const float* __restrict__ b_ih, const float* __restrict__ b_hh,
    const float* __restrict__ conv_w, const float* __restrict__ conv_b,
    const float* __restrict__ attn_w, const float* __restrict__ attn_b,
    const float* __restrict__ fc_w, const float* __restrict__ fc_b,
    float* __restrict__ out, float* __restrict__ aligns)
{
    __shared__ SmemT sm;
    const int bid = blockIdx.x;
    const int tid = threadIdx.x;
    const int w = tid >> 5, lane = tid & 31;

    unsigned barn = 0;   // absolute barrier index; g_bar starts at 0 this launch

    #define GRID_BARRIER() do {                                              \
        barn++;                                                              \
        __syncthreads();                                                     \
        if (tid == 0) {                                                      \
            __threadfence();                                                 \
            atomicAdd(&g_bar, 1u);                                           \
            unsigned target = barn * NBLK;                                   \
            while ((int)(*((volatile unsigned*)&g_bar) - target) < 0)        \
                __nanosleep(32);                                             \
        }                                                                    \
        __syncthreads();                                                     \
    } while (0)

    for (int t = 0; t < Lsteps; t++) {
        const int rd = t & 1, wr = rd ^ 1;

        // ================= phase 1: GRU + fc(t-1), 2 units per block ========
        #pragma unroll 1
        for (int u = 0; u < 2; u++) {
            int unit = bid * 2 + u;
            int ht = unit >> 2, bt = unit & 3;
            int h0 = ht << 3, b0 = bt << 3;

            __syncthreads();
            for (int idx = tid; idx < 8 * Hd; idx += 512) {
                int bb = idx >> 9, i = idx & 511;
                int b = b0 + bb;
                int tok = y[b * 101 + t];
                float sxv = (t > 0) ? __ldcg(&g_sx[b * Hd + i]) : 0.0f;
                sm.p1.ix[bb][i] = emb[(size_t)tok * Hd + i] + sxv;
                sm.p1.sx[bb][i] = sxv;
                sm.p1.hx[bb][i] = (t > 0) ? __ldcg(&g_hx[rd][b * Hd + i]) : 0.0f;
            }
            __syncthreads();

            // GRU: warp w -> h = h0 + (w&7), b-half (w>>3)*4 .. +4
            int h = h0 + (w & 7);
            int bs = (w >> 3) << 2;
            const float* wi0 = W_ih + (size_t)h * Hd;
            const float* wi1 = W_ih + (size_t)(Hd + h) * Hd;
            const float* wi2 = W_ih + (size_t)(2 * Hd + h) * Hd;
            const float* wh0 = W_hh + (size_t)h * Hd;
            const float* wh1 = W_hh + (size_t)(Hd + h) * Hd;
            const float* wh2 = W_hh + (size_t)(2 * Hd + h) * Hd;

            float acc[6][4];
            #pragma unroll
            for (int g = 0; g < 6; g++)
                #pragma unroll
                for (int bb = 0; bb < 4; bb++) acc[g][bb] = 0.0f;

            for (int i = lane; i < Hd; i += 32) {
                float w0 = wi0[i], w1 = wi1[i], w2 = wi2[i];
                float w3 = wh0[i], w4 = wh1[i], w5 = wh2[i];
                #pragma unroll
                for (int bb = 0; bb < 4; bb++) {
                    float xi = sm.p1.ix[bs + bb][i];
                    float xh = sm.p1.hx[bs + bb][i];
                    acc[0][bb] = fmaf(w0, xi, acc[0][bb]);
                    acc[1][bb] = fmaf(w1, xi, acc[1][bb]);
                    acc[2][bb] = fmaf(w2, xi, acc[2][bb]);
                    acc[3][bb] = fmaf(w3, xh, acc[3][bb]);
                    acc[4][bb] = fmaf(w4, xh, acc[4][bb]);
                    acc[5][bb] = fmaf(w5, xh, acc[5][bb]);
                }
            }
            #pragma unroll
            for (int g = 0; g < 6; g++)
                #pragma unroll
                for (int bb = 0; bb < 4; bb++) acc[g][bb] = warp_sum(acc[g][bb]);

            if (lane < 4) {
                int bb = bs + lane;
                int b = b0 + bb;
                float gr = acc[0][lane] + b_ih[h] + acc[3][lane] + b_hh[h];
                float gz = acc[1][lane] + b_ih[Hd + h] + acc[4][lane] + b_hh[Hd + h];
                float r = 1.0f / (1.0f + expf(-gr));
                float z = 1.0f / (1.0f + expf(-gz));
                float n = tanhf(acc[2][lane] + b_ih[2 * Hd + h] +
                                r * (acc[5][lane] + b_hh[2 * Hd + h]));
                float hp = sm.p1.hx[bb][h];
                g_hx[wr][b * Hd + h] = (1.0f - z) * n + z * hp;
            }

            // fc(t-1): same (vt=unit>>2, bt) decomposition; reuse hx/sx smem
            if (t > 0) {
                int v = (ht << 3) + (w & 7);   // vt == ht
                if (v < Vout) {
                    const float* fw = fc_w + (size_t)v * Hd;
                    float facc[4];
                    #pragma unroll
                    for (int bb = 0; bb < 4; bb++) facc[bb] = 0.0f;
                    for (int i = lane; i < Hd; i += 32) {
                        float wv = fw[i];
                        #pragma unroll
                        for (int bb = 0; bb < 4; bb++)
                            facc[bb] = fmaf(wv, sm.p1.hx[bs + bb][i] + sm.p1.sx[bs + bb][i],
                                            facc[bb]);
                    }
                    #pragma unroll
                    for (int bb = 0; bb < 4; bb++) facc[bb] = warp_sum(facc[bb]);
                    if (lane < 4) {
                        int b = b0 + bs + lane;
                        out[(size_t)b * Lsteps * Vout + (size_t)(t - 1) * Vout + v] =
                            facc[lane] + fc_b[v];
                    }
                }
            }
        }
        GRID_BARRIER();

        // ================= phase 2: attention scores ========================
        {
            int b = bid >> 2;
            int T0 = (bid & 3) * 100;
            int h = (w << 5) + lane;

            if (tid < 114) {
                int j = T0 - 7 + tid;
                float v = 0.0f;
                if (t > 0 && j >= 0 && j < Tenc)
                    v = __ldcg(&aligns[(size_t)b * Lsteps * Tenc +
                                       (size_t)(t - 1) * Tenc + j]);
                sm.p2.win[tid] = v;
            }

            float cw[KS];
            #pragma unroll
            for (int k = 0; k < KS; k++) cw[k] = conv_w[h * KS + k];
            float cbv   = conv_b[h];
            float attwv = attn_w[h];
            float hxv   = __ldcg(&g_hx[wr][b * Hd + h]);
            __syncthreads();

            const float* xb = x + (size_t)b * Tenc * Hd + h;

            #pragma unroll 1
            for (int tc = 0; tc < 10; tc++) {
                int tl0 = tc * 10;
                float xv[10];
                #pragma unroll
                for (int i = 0; i < 10; i++)
                    xv[i] = xb[(size_t)(T0 + tl0 + i) * Hd];
                float wvr[24];
                #pragma unroll
                for (int j = 0; j < 24; j++) wvr[j] = sm.p2.win[tl0 + j];

                float part[10];
                #pragma unroll
                for (int i = 0; i < 10; i++) {
                    float p = xv[i] + hxv;
                    if (t > 0) {
                        float conv = cbv;
                        #pragma unroll
                        for (int k = 0; k < KS; k++)
                            conv = fmaf(cw[k], wvr[i + k], conv);
                        p += conv;
                    }
                    part[i] = fmaxf(p, 0.0f) * attwv;
                }
                #pragma unroll
                for (int i = 0; i < 10; i++) part[i] = warp_sum(part[i]);
                if (lane == 0) {
                    #pragma unroll
                    for (int i = 0; i < 10; i++) sm.p2.part[w][tl0 + i] = part[i];
                }
            }
            __syncthreads();
            if (tid < 100) {
                float s = 0.0f;
                #pragma unroll
                for (int c2 = 0; c2 < 16; c2++) s += sm.p2.part[c2][tid];
                g_scores[b * Tenc + T0 + tid] = s + attn_b[0];
            }
        }
        GRID_BARRIER();

        // ================= phase 3: softmax + context =======================
        {
            int b = bid >> 2;
            int ht = bid & 3;
            int h0 = ht << 7;

            float sv = (tid < Tenc) ? __ldcg(&g_scores[b * Tenc + tid]) : -1e30f;
            float m = warp_max(sv);
            if (lane == 0) sm.p3.red[w] = m;
            __syncthreads();
            float bm = -1e30f;
            #pragma unroll
            for (int j = 0; j < 16; j++) bm = fmaxf(bm, sm.p3.red[j]);

            float e = (tid < Tenc) ? __expf(sv - bm) : 0.0f;
            if (tid < Tenc) sm.p3.a[tid] = e;
            float sum = warp_sum(e);
            __syncthreads();
            if (lane == 0) sm.p3.red[w] = sum;
            __syncthreads();
            float tot = 0.0f;
            #pragma unroll
            for (int j = 0; j < 16; j++) tot += sm.p3.red[j];
            float inv = 1.0f / tot;

            const float4* xb4 =
                (const float4*)(x + (size_t)b * Tenc * Hd) + (h0 >> 2) + lane;
            int t0 = w * 25;
            float4 acc[5];
            #pragma unroll
            for (int j = 0; j < 5; j++) acc[j] = make_float4(0.f, 0.f, 0.f, 0.f);
            #pragma unroll
            for (int i = 0; i < 25; i++) {
                int tt = t0 + i;
                float a = sm.p3.a[tt];
                float4 xv = xb4[(size_t)tt * (Hd / 4)];
                float4& A = acc[i % 5];
                A.x = fmaf(a, xv.x, A.x);
                A.y = fmaf(a, xv.y, A.y);
                A.z = fmaf(a, xv.z, A.z);
                A.w = fmaf(a, xv.w, A.w);
            }
            float4 r = acc[0];
            #pragma unroll
            for (int j = 1; j < 5; j++) {
                r.x += acc[j].x; r.y += acc[j].y; r.z += acc[j].z; r.w += acc[j].w;
            }
            sm.p3.ctx[w][lane] = r;
            __syncthreads();
            if (tid < 32) {
                float4 a2 = make_float4(0.f, 0.f, 0.f, 0.f);
                #pragma unroll
                for (int g = 0; g < 16; g++) {
                    float4 v = sm.p3.ctx[g][tid];
                    a2.x += v.x; a2.y += v.y; a2.z += v.z; a2.w += v.w;
                }
                a2.x *= inv; a2.y *= inv; a2.z *= inv; a2.w *= inv;
                *(float4*)(g_sx + b * Hd + h0 + tid * 4) = a2;
            }
            if (ht == 0 && tid < Tenc)
                aligns[(size_t)b * Lsteps * Tenc + (size_t)t * Tenc + tid] =
                    sm.p3.a[tid] * inv;
        }
        GRID_BARRIER();
    }

    // ================= final fc for step 99 (hx in buffer 0) =================
    #pragma unroll 1
    for (int u = 0; u < 2; u++) {
        int unit = bid * 2 + u;
        int vt = unit >> 2, bt = unit & 3;
        int b0 = bt << 3;
        __syncthreads();
        for (int idx = tid; idx < 8 * Hd; idx += 512) {
            int bb = idx >> 9, i = idx & 511;
            int b = b0 + bb;
            sm.pf.in[bb][i] = __ldcg(&g_hx[0][b * Hd + i]) + __ldcg(&g_sx[b * Hd + i]);
        }
        __syncthreads();
        int v = (vt << 3) + (w & 7);
        int bs = (w >> 3) << 2;
        if (v < Vout) {
            const float* fw = fc_w + (size_t)v * Hd;
            float facc[4];
            #pragma unroll
            for (int bb = 0; bb < 4; bb++) facc[bb] = 0.0f;
            for (int i = lane; i < Hd; i += 32) {
                float wv = fw[i];
                #pragma unroll
                for (int bb = 0; bb < 4; bb++)
                    facc[bb] = fmaf(wv, sm.pf.in[bs + bb][i], facc[bb]);
            }
            #pragma unroll
            for (int bb = 0; bb < 4; bb++) facc[bb] = warp_sum(facc[bb]);
            if (lane < 4) {
                int b = b0 + bs + lane;
                out[(size_t)b * Lsteps * Vout + (size_t)(Lsteps - 1) * Vout + v] =
                    facc[lane] + fc_b[v];
            }
        }
    }
    #undef GRID_BARRIER
}

// ---------------- launch ------------------------------------------------------
extern "C" void kernel_launch(void* const* d_in, const int* in_sizes, int n_in,
                              void* d_out, int out_size)
{
    const float* x      = (const float*)d_in[0];
    const int*   y      = (const int*)  d_in[1];
    const float* emb    = (const float*)d_in[2];
    const float* W_ih   = (const float*)d_in[3];
    const float* W_hh   = (const float*)d_in[4];
    const float* b_ih   = (const float*)d_in[5];
    const float* b_hh   = (const float*)d_in[6];
    const float* conv_w = (const float*)d_in[7];
    const float* conv_b = (const float*)d_in[8];
    const float* attn_w = (const float*)d_in[9];
    const float* attn_b = (const float*)d_in[10];
    const float* fc_w   = (const float*)d_in[11];
    const float* fc_b   = (const float*)d_in[12];

    float* out    = (float*)d_out;
    float* aligns = out + (size_t)Bsz * Lsteps * Vout;

    bar_init<<<1, 1>>>();
    seq2seq_persist<<<NBLK, 512>>>(x, y, emb, W_ih, W_hh, b_ih, b_hh,
                                   conv_w, conv_b, attn_w, attn_b,
                                   fc_w, fc_b, out, aligns);
}

// round 8
// speedup vs baseline: 1.5458x; 1.5458x over previous
#include <cuda_runtime.h>

#define Bsz 32
#define Tenc 400
#define Hd 512
#define Lsteps 100
#define Vout 511
#define KS 15
#define NBLK 128

// ---------------- persistent state ------------------------------------------
__device__ float g_hx[2][Bsz * Hd];
__device__ float g_ctxp[4][Bsz * Hd];   // per-t-tile partial contexts (x inv)
__device__ float g_scores[Bsz * Tenc];
__device__ unsigned g_bar;              // zeroed by bar_init each launch

__device__ __forceinline__ float warp_sum(float v) {
    #pragma unroll
    for (int o = 16; o; o >>= 1) v += __shfl_xor_sync(0xffffffffu, v, o);
    return v;
}
__device__ __forceinline__ float warp_max(float v) {
    #pragma unroll
    for (int o = 16; o; o >>= 1) v = fmaxf(v, __shfl_xor_sync(0xffffffffu, v, o));
    return v;
}

// ---- f32x2 packed math ------------------------------------------------------
typedef unsigned long long u64;
__device__ __forceinline__ u64 pack2(float lo, float hi) {
    u64 r;
    asm("mov.b64 %0, {%1, %2};" : "=l"(r) : "f"(lo), "f"(hi));
    return r;
}
__device__ __forceinline__ void unpack2(u64 v, float& lo, float& hi) {
    asm("mov.b64 {%0, %1}, %2;" : "=f"(lo), "=f"(hi) : "l"(v));
}
__device__ __forceinline__ void fma2(u64& d, u64 a, u64 b) {
    asm("fma.rn.f32x2 %0, %1, %2, %0;" : "+l"(d) : "l"(a), "l"(b));
}

__global__ void bar_init() { g_bar = 0u; }

struct SmemT {
    union {
        struct { float ix[8][Hd]; float hx[8][Hd]; float fin[8][Hd]; } p1; // 48KB
        struct { float win[128]; float part[16][100]; } p2;
        struct { float a[Tenc]; float red[16]; } p3;
    };
};

__global__ void __launch_bounds__(512, 1) seq2seq_persist(
    const float* __restrict__ x, const int* __restrict__ y,
    const float* __restrict__ emb,
    const float* __restrict__ W_ih, const float* __restrict__ W_hh,
    const float* __restrict__ b_ih, const float* __restrict__ b_hh,
    const float* __restrict__ conv_w, const float* __restrict__ conv_b,
    const float* __restrict__ attn_w, const float* __restrict__ attn_b,
    const float* __restrict__ fc_w, const float* __restrict__ fc_b,
    float* __restrict__ out, float* __restrict__ aligns)
{
    __shared__ SmemT sm;
    const int bid = blockIdx.x;
    const int tid = threadIdx.x;
    const int w = tid >> 5, lane = tid & 31;

    unsigned barn = 0;

    #define GRID_BARRIER() do {                                              \
        barn++;                                                              \
        __syncthreads();                                                     \
        if (tid == 0) {                                                      \
            __threadfence();                                                 \
            atomicAdd(&g_bar, 1u);                                           \
            unsigned target = barn * NBLK;                                   \
            while ((int)(*((volatile unsigned*)&g_bar) - target) < 0)        \
                __nanosleep(32);                                             \
        }                                                                    \
        __syncthreads();                                                     \
    } while (0)

    for (int t = 0; t < Lsteps; t++) {
        const int rd = t & 1, wr = rd ^ 1;

        // ===== phase 1: GRU + fc(t-1). block = (ht 16h, bt 8b); warp=(1h,8b) =
        {
            const int bt = bid & 3, ht = bid >> 2;
            const int b0 = bt << 3;
            const int h = (ht << 4) + w;     // GRU output row
            const int v = (ht << 4) + w;     // fc row (skip 511)

            for (int idx = tid; idx < 8 * Hd; idx += 512) {
                int bb = idx >> 9, i = idx & 511;
                int b = b0 + bb;
                int tok = y[b * 101 + t];
                float sxv = 0.0f, hxv = 0.0f;
                if (t > 0) {
                    sxv = __ldcg(&g_ctxp[0][b * Hd + i]) +
                          __ldcg(&g_ctxp[1][b * Hd + i]) +
                          __ldcg(&g_ctxp[2][b * Hd + i]) +
                          __ldcg(&g_ctxp[3][b * Hd + i]);
                    hxv = __ldcg(&g_hx[rd][b * Hd + i]);
                }
                sm.p1.ix[bb][i]  = emb[(size_t)tok * Hd + i] + sxv;
                sm.p1.hx[bb][i]  = hxv;
                sm.p1.fin[bb][i] = hxv + sxv;
            }
            __syncthreads();

            const float* wi0 = W_ih + (size_t)h * Hd;
            const float* wi1 = W_ih + (size_t)(Hd + h) * Hd;
            const float* wi2 = W_ih + (size_t)(2 * Hd + h) * Hd;
            const float* wh0 = W_hh + (size_t)h * Hd;
            const float* wh1 = W_hh + (size_t)(Hd + h) * Hd;
            const float* wh2 = W_hh + (size_t)(2 * Hd + h) * Hd;
            const float* fw  = fc_w + (size_t)(v < Vout ? v : 0) * Hd;

            float acc[6][8], fac[8];
            #pragma unroll
            for (int g = 0; g < 6; g++)
                #pragma unroll
                for (int bb = 0; bb < 8; bb++) acc[g][bb] = 0.0f;
            #pragma unroll
            for (int bb = 0; bb < 8; bb++) fac[bb] = 0.0f;

            for (int i = lane; i < Hd; i += 32) {
                float w0 = wi0[i], w1 = wi1[i], w2 = wi2[i];
                float w3 = wh0[i], w4 = wh1[i], w5 = wh2[i];
                float w6 = fw[i];
                #pragma unroll
                for (int bb = 0; bb < 8; bb++) {
                    float xi = sm.p1.ix[bb][i];
                    float xh = sm.p1.hx[bb][i];
                    float xf = sm.p1.fin[bb][i];
                    acc[0][bb] = fmaf(w0, xi, acc[0][bb]);
                    acc[1][bb] = fmaf(w1, xi, acc[1][bb]);
                    acc[2][bb] = fmaf(w2, xi, acc[2][bb]);
                    acc[3][bb] = fmaf(w3, xh, acc[3][bb]);
                    acc[4][bb] = fmaf(w4, xh, acc[4][bb]);
                    acc[5][bb] = fmaf(w5, xh, acc[5][bb]);
                    fac[bb]    = fmaf(w6, xf, fac[bb]);
                }
            }
            #pragma unroll
            for (int g = 0; g < 6; g++)
                #pragma unroll
                for (int bb = 0; bb < 8; bb++) acc[g][bb] = warp_sum(acc[g][bb]);
            #pragma unroll
            for (int bb = 0; bb < 8; bb++) fac[bb] = warp_sum(fac[bb]);

            if (lane < 8) {
                int bb = lane, b = b0 + bb;
                float gr = acc[0][bb] + b_ih[h] + acc[3][bb] + b_hh[h];
                float gz = acc[1][bb] + b_ih[Hd + h] + acc[4][bb] + b_hh[Hd + h];
                float r = 1.0f / (1.0f + expf(-gr));
                float z = 1.0f / (1.0f + expf(-gz));
                float n = tanhf(acc[2][bb] + b_ih[2 * Hd + h] +
                                r * (acc[5][bb] + b_hh[2 * Hd + h]));
                float hp = sm.p1.hx[bb][h];
                g_hx[wr][b * Hd + h] = (1.0f - z) * n + z * hp;
                if (t > 0 && v < Vout)
                    out[(size_t)b * Lsteps * Vout + (size_t)(t - 1) * Vout + v] =
                        fac[bb] + fc_b[v];
            }
        }
        GRID_BARRIER();

        // ===== phase 2: attention scores. block = (b, t-tile 100) ===========
        {
            int b = bid >> 2;
            int T0 = (bid & 3) * 100;
            int h = (w << 5) + lane;

            if (tid < 114) {
                int j = T0 - 7 + tid;
                float vv = 0.0f;
                if (t > 0 && j >= 0 && j < Tenc)
                    vv = __ldcg(&aligns[(size_t)b * Lsteps * Tenc +
                                        (size_t)(t - 1) * Tenc + j]);
                sm.p2.win[tid] = vv;
            }

            float cw[KS];
            #pragma unroll
            for (int k = 0; k < KS; k++) cw[k] = conv_w[h * KS + k];
            u64 cwp[7];
            #pragma unroll
            for (int m = 0; m < 7; m++) cwp[m] = pack2(cw[2 * m], cw[2 * m + 1]);
            float cw14  = cw[14];
            float cbv   = conv_b[h];
            float attwv = attn_w[h];
            float hxv   = __ldcg(&g_hx[wr][b * Hd + h]);
            __syncthreads();

            const float* xb = x + (size_t)b * Tenc * Hd + h;

            if (t > 0) {
                #pragma unroll 1
                for (int tc = 0; tc < 10; tc++) {
                    int tl0 = tc * 10;
                    float xv[10];
                    #pragma unroll
                    for (int i = 0; i < 10; i++)
                        xv[i] = xb[(size_t)(T0 + tl0 + i) * Hd];
                    float wvr[24];
                    #pragma unroll
                    for (int j = 0; j < 24; j++) wvr[j] = sm.p2.win[tl0 + j];

                    {   // even i: pairs at even offsets
                        u64 Pe[11];
                        #pragma unroll
                        for (int m = 0; m < 11; m++)
                            Pe[m] = pack2(wvr[2 * m], wvr[2 * m + 1]);
                        #pragma unroll
                        for (int i = 0; i < 10; i += 2) {
                            int j = i >> 1;
                            u64 a2 = pack2(cbv, 0.0f);
                            #pragma unroll
                            for (int m = 0; m < 7; m++) fma2(a2, cwp[m], Pe[j + m]);
                            float lo, hi; unpack2(a2, lo, hi);
                            float conv = lo + hi + cw14 * wvr[i + 14];
                            float p = xv[i] + hxv + conv;
                            float part = warp_sum(fmaxf(p, 0.0f) * attwv);
                            if (lane == 0) sm.p2.part[w][tl0 + i] = part;
                        }
                    }
                    {   // odd i: pairs at odd offsets
                        u64 Po[11];
                        #pragma unroll
                        for (int m = 0; m < 11; m++)
                            Po[m] = pack2(wvr[2 * m + 1], wvr[2 * m + 2]);
                        #pragma unroll
                        for (int i = 1; i < 10; i += 2) {
                            int j = (i - 1) >> 1;
                            u64 a2 = pack2(cbv, 0.0f);
                            #pragma unroll
                            for (int m = 0; m < 7; m++) fma2(a2, cwp[m], Po[j + m]);
                            float lo, hi; unpack2(a2, lo, hi);
                            float conv = lo + hi + cw14 * wvr[i + 14];
                            float p = xv[i] + hxv + conv;
                            float part = warp_sum(fmaxf(p, 0.0f) * attwv);
                            if (lane == 0) sm.p2.part[w][tl0 + i] = part;
                        }
                    }
                }
            } else {
                #pragma unroll 1
                for (int tc = 0; tc < 10; tc++) {
                    int tl0 = tc * 10;
                    float xv[10];
                    #pragma unroll
                    for (int i = 0; i < 10; i++)
                        xv[i] = xb[(size_t)(T0 + tl0 + i) * Hd];
                    #pragma unroll
                    for (int i = 0; i < 10; i++) {
                        float p = xv[i] + hxv;
                        float part = warp_sum(fmaxf(p, 0.0f) * attwv);
                        if (lane == 0) sm.p2.part[w][tl0 + i] = part;
                    }
                }
            }
            __syncthreads();
            if (tid < 100) {
                float s = 0.0f;
                #pragma unroll
                for (int c2 = 0; c2 < 16; c2++) s += sm.p2.part[c2][tid];
                g_scores[b * Tenc + T0 + tid] = s + attn_b[0];
            }
        }
        GRID_BARRIER();

        // ===== phase 3: softmax + PARTIAL context. block = (b, t-tile 100) ===
        {
            int b = bid >> 2;
            int tile = bid & 3;
            int T0 = tile * 100;

            float sv = (tid < Tenc) ? __ldcg(&g_scores[b * Tenc + tid]) : -1e30f;
            float m = warp_max(sv);
            if (lane == 0) sm.p3.red[w] = m;
            __syncthreads();
            float bm = -1e30f;
            #pragma unroll
            for (int j = 0; j < 16; j++) bm = fmaxf(bm, sm.p3.red[j]);

            float e = (tid < Tenc) ? __expf(sv - bm) : 0.0f;
            if (tid < Tenc) sm.p3.a[tid] = e;
            float sum = warp_sum(e);
            __syncthreads();
            if (lane == 0) sm.p3.red[w] = sum;
            __syncthreads();
            float tot = 0.0f;
            #pragma unroll
            for (int j = 0; j < 16; j++) tot += sm.p3.red[j];
            float inv = 1.0f / tot;

            // partial ctx over t in [T0, T0+100) for h = tid (contiguous rows)
            const float* xb = x + (size_t)b * Tenc * Hd + (size_t)T0 * Hd + tid;
            float acc[5];
            #pragma unroll
            for (int j = 0; j < 5; j++) acc[j] = 0.0f;
            #pragma unroll 1
            for (int c = 0; c < 10; c++) {
                int i0 = c * 10;
                float xr[10];
                #pragma unroll
                for (int i = 0; i < 10; i++)
                    xr[i] = xb[(size_t)(i0 + i) * Hd];
                #pragma unroll
                for (int i = 0; i < 10; i++)
                    acc[i % 5] = fmaf(sm.p3.a[T0 + i0 + i], xr[i], acc[i % 5]);
            }
            float r = (acc[0] + acc[1]) + (acc[2] + acc[3]) + acc[4];
            g_ctxp[tile][b * Hd + tid] = r * inv;

            if (tid < 100)
                aligns[(size_t)b * Lsteps * Tenc + (size_t)t * Tenc + T0 + tid] =
                    sm.p3.a[T0 + tid] * inv;
        }
        GRID_BARRIER();
    }

    // ===== final fc for step 99 (hx in buffer 0) ============================
    {
        const int bt = bid & 3, vt = bid >> 2;
        const int b0 = bt << 3;
        const int v = (vt << 4) + w;

        for (int idx = tid; idx < 8 * Hd; idx += 512) {
            int bb = idx >> 9, i = idx & 511;
            int b = b0 + bb;
            float sxv = __ldcg(&g_ctxp[0][b * Hd + i]) +
                        __ldcg(&g_ctxp[1][b * Hd + i]) +
                        __ldcg(&g_ctxp[2][b * Hd + i]) +
                        __ldcg(&g_ctxp[3][b * Hd + i]);
            sm.p1.fin[bb][i] = __ldcg(&g_hx[0][b * Hd + i]) + sxv;
        }
        __syncthreads();

        if (v < Vout) {
            const float* fw = fc_w + (size_t)v * Hd;
            float fac[8];
            #pragma unroll
            for (int bb = 0; bb < 8; bb++) fac[bb] = 0.0f;
            for (int i = lane; i < Hd; i += 32) {
                float wv = fw[i];
                #pragma unroll
                for (int bb = 0; bb < 8; bb++)
                    fac[bb] = fmaf(wv, sm.p1.fin[bb][i], fac[bb]);
            }
            #pragma unroll
            for (int bb = 0; bb < 8; bb++) fac[bb] = warp_sum(fac[bb]);
            if (lane < 8) {
                int b = b0 + lane;
                out[(size_t)b * Lsteps * Vout + (size_t)(Lsteps - 1) * Vout + v] =
                    fac[lane] + fc_b[v];
            }
        }
    }
    #undef GRID_BARRIER
}

// ---------------- launch ------------------------------------------------------
extern "C" void kernel_launch(void* const* d_in, const int* in_sizes, int n_in,
                              void* d_out, int out_size)
{
    const float* x      = (const float*)d_in[0];
    const int*   y      = (const int*)  d_in[1];
    const float* emb    = (const float*)d_in[2];
    const float* W_ih   = (const float*)d_in[3];
    const float* W_hh   = (const float*)d_in[4];
    const float* b_ih   = (const float*)d_in[5];
    const float* b_hh   = (const float*)d_in[6];
    const float* conv_w = (const float*)d_in[7];
    const float* conv_b = (const float*)d_in[8];
    const float* attn_w = (const float*)d_in[9];
    const float* attn_b = (const float*)d_in[10];
    const float* fc_w   = (const float*)d_in[11];
    const float* fc_b   = (const float*)d_in[12];

    float* out    = (float*)d_out;
    float* aligns = out + (size_t)Bsz * Lsteps * Vout;

    bar_init<<<1, 1>>>();
    seq2seq_persist<<<NBLK, 512>>>(x, y, emb, W_ih, W_hh, b_ih, b_hh,
                                   conv_w, conv_b, attn_w, attn_b,
                                   fc_w, fc_b, out, aligns);
}